// round 3
// baseline (speedup 1.0000x reference)
#include <cuda_runtime.h>
#include <math.h>

// Problem constants
#define S_LEN   2048
#define H_DIM   4096
#define NHEADS  32
#define HD      128
#define K3      12288            // 3*H
#define INV_NORM 0.08838834764831845f   // 1/sqrt(128)

// Scratch (device globals: allocation-free)
__device__ float g_fused[(size_t)S_LEN * K3];   // [S, NH, 3, HD] = [2048, 12288]
__device__ float g_ctx[(size_t)S_LEN * H_DIM];  // [S, H]

// ---------------------------------------------------------------------------
// GEMM: C[M,N] = A[M,K] @ B[N,K]^T + bias[N] (+ resid[M,N])
// 128x128 tile, BK=8, 256 threads, 8x8 register tile per thread.
// ---------------------------------------------------------------------------
template<bool ADD_RES>
__global__ __launch_bounds__(256) void gemm_kernel(
    const float* __restrict__ A, const float* __restrict__ Bw,
    const float* __restrict__ bias, const float* __restrict__ resid,
    float* __restrict__ C, int M, int N, int K)
{
    __shared__ float As[8][132];
    __shared__ float Bs[8][132];

    const int tid  = threadIdx.x;
    const int tx   = tid & 15;       // 0..15 -> N direction
    const int ty   = tid >> 4;       // 0..15 -> M direction
    const int lrow = tid >> 1;       // 0..127 load row
    const int lcol = (tid & 1) * 4;  // 0 or 4

    const float* Ab = A  + (size_t)blockIdx.y * 128 * K;
    const float* Bb = Bw + (size_t)blockIdx.x * 128 * K;

    float acc[8][8];
#pragma unroll
    for (int i = 0; i < 8; i++)
#pragma unroll
        for (int j = 0; j < 8; j++) acc[i][j] = 0.f;

    for (int k0 = 0; k0 < K; k0 += 8) {
        float4 a4 = *(const float4*)(Ab + (size_t)lrow * K + k0 + lcol);
        float4 b4 = *(const float4*)(Bb + (size_t)lrow * K + k0 + lcol);
        As[lcol + 0][lrow] = a4.x; As[lcol + 1][lrow] = a4.y;
        As[lcol + 2][lrow] = a4.z; As[lcol + 3][lrow] = a4.w;
        Bs[lcol + 0][lrow] = b4.x; Bs[lcol + 1][lrow] = b4.y;
        Bs[lcol + 2][lrow] = b4.z; Bs[lcol + 3][lrow] = b4.w;
        __syncthreads();
#pragma unroll
        for (int kk = 0; kk < 8; kk++) {
            float a[8], b[8];
#pragma unroll
            for (int i = 0; i < 8; i++) a[i] = As[kk][ty * 8 + i];
#pragma unroll
            for (int j = 0; j < 8; j++) b[j] = Bs[kk][tx * 8 + j];
#pragma unroll
            for (int i = 0; i < 8; i++)
#pragma unroll
                for (int j = 0; j < 8; j++)
                    acc[i][j] += a[i] * b[j];
        }
        __syncthreads();
    }

#pragma unroll
    for (int i = 0; i < 8; i++) {
        const int row = blockIdx.y * 128 + ty * 8 + i;
#pragma unroll
        for (int j = 0; j < 8; j++) {
            const int col = blockIdx.x * 128 + tx * 8 + j;
            float v = acc[i][j] + bias[col];
            if (ADD_RES) v += resid[(size_t)row * N + col];
            C[(size_t)row * N + col] = v;
        }
    }
}

// ---------------------------------------------------------------------------
// Flash attention (fp32, causal + alibi), per (q-tile 64, head) block.
// q/k/v read directly from g_fused at [s, h*384 + {0,128,256} + d].
// ---------------------------------------------------------------------------
#define AQ  64
#define AKV 64
#define QP  132            // padded pitch for 128-wide tiles
#define SP  68             // padded pitch for 64-wide score tile
#define NEG_INF -1e30f
#define ATTN_SMEM ((AQ*QP + 2*AKV*QP + AQ*SP) * 4)   // 118784 B

__global__ __launch_bounds__(256) void attn_kernel(const float* __restrict__ alibi)
{
    extern __shared__ float sm[];
    float* Qs = sm;                    // [64][132]
    float* Ks = Qs + AQ * QP;          // [64][132]
    float* Vs = Ks + AKV * QP;         // [64][132]
    float* Sc = Vs + AKV * QP;         // [64][68]

    const int q0  = blockIdx.x * AQ;
    const int h   = blockIdx.y;
    const int tid = threadIdx.x;
    const int tr  = tid >> 4;          // 0..15 (row group)
    const int tc  = tid & 15;          // 0..15 (col group)

    // Load Q tile: rows r own fused[(q0+r)*K3 + h*384 + 0..127]
    {
        const float* qbase = g_fused + (size_t)q0 * K3 + h * 384;
        for (int idx = tid; idx < AQ * 32; idx += 256) {
            const int r  = idx >> 5;
            const int c4 = (idx & 31) << 2;
            *(float4*)(Qs + r * QP + c4) =
                *(const float4*)(qbase + (size_t)r * K3 + c4);
        }
    }

    float m_i[4], l_i[4], o[4][8];
#pragma unroll
    for (int i = 0; i < 4; i++) {
        m_i[i] = NEG_INF; l_i[i] = 0.f;
#pragma unroll
        for (int d = 0; d < 8; d++) o[i][d] = 0.f;
    }

    const float* alibi_h = alibi + (size_t)h * S_LEN;
    const int nkt = (q0 / AKV) + 1;    // causal: only kv tiles with kc <= q0

    for (int kt = 0; kt < nkt; kt++) {
        const int kc = kt * AKV;
        // Load K, V tiles
        {
            const float* kbase = g_fused + (size_t)kc * K3 + h * 384 + 128;
            const float* vbase = kbase + 128;
            for (int idx = tid; idx < AKV * 32; idx += 256) {
                const int r  = idx >> 5;
                const int c4 = (idx & 31) << 2;
                *(float4*)(Ks + r * QP + c4) =
                    *(const float4*)(kbase + (size_t)r * K3 + c4);
                *(float4*)(Vs + r * QP + c4) =
                    *(const float4*)(vbase + (size_t)r * K3 + c4);
            }
        }
        __syncthreads();

        // QK^T: each thread computes 4x4 scores at rows tr+16i, cols tc+16j
        float acc[4][4];
#pragma unroll
        for (int i = 0; i < 4; i++)
#pragma unroll
            for (int j = 0; j < 4; j++) acc[i][j] = 0.f;

#pragma unroll 8
        for (int k = 0; k < HD; k += 4) {
            float4 qv[4], kv[4];
#pragma unroll
            for (int i = 0; i < 4; i++)
                qv[i] = *(const float4*)(Qs + (tr + 16 * i) * QP + k);
#pragma unroll
            for (int j = 0; j < 4; j++)
                kv[j] = *(const float4*)(Ks + (tc + 16 * j) * QP + k);
#pragma unroll
            for (int i = 0; i < 4; i++)
#pragma unroll
                for (int j = 0; j < 4; j++) {
                    acc[i][j] += qv[i].x * kv[j].x;
                    acc[i][j] += qv[i].y * kv[j].y;
                    acc[i][j] += qv[i].z * kv[j].z;
                    acc[i][j] += qv[i].w * kv[j].w;
                }
        }

        // scale + alibi + causal mask + online softmax (per owned row)
#pragma unroll
        for (int i = 0; i < 4; i++) {
            const int r = q0 + tr + 16 * i;
            float s[4];
            float mx = NEG_INF;
#pragma unroll
            for (int j = 0; j < 4; j++) {
                const int c = kc + tc + 16 * j;
                s[j] = (c <= r) ? acc[i][j] * INV_NORM + __ldg(&alibi_h[c])
                                : NEG_INF;
                mx = fmaxf(mx, s[j]);
            }
            // reduce max across the 16 threads sharing this row (contiguous lanes)
            mx = fmaxf(mx, __shfl_xor_sync(0xffffffffu, mx, 1));
            mx = fmaxf(mx, __shfl_xor_sync(0xffffffffu, mx, 2));
            mx = fmaxf(mx, __shfl_xor_sync(0xffffffffu, mx, 4));
            mx = fmaxf(mx, __shfl_xor_sync(0xffffffffu, mx, 8));

            const float m_new = fmaxf(m_i[i], mx);
            const float scale = __expf(m_i[i] - m_new);
            m_i[i] = m_new;

            float ps = 0.f;
#pragma unroll
            for (int j = 0; j < 4; j++) {
                const float p = __expf(s[j] - m_new);
                Sc[(tr + 16 * i) * SP + tc + 16 * j] = p;
                ps += p;
            }
            ps += __shfl_xor_sync(0xffffffffu, ps, 1);
            ps += __shfl_xor_sync(0xffffffffu, ps, 2);
            ps += __shfl_xor_sync(0xffffffffu, ps, 4);
            ps += __shfl_xor_sync(0xffffffffu, ps, 8);

            l_i[i] = l_i[i] * scale + ps;
#pragma unroll
            for (int d = 0; d < 8; d++) o[i][d] *= scale;
        }
        __syncthreads();

        // P @ V: thread owns rows tr+16i, head-dims d = tc*8 .. tc*8+7
#pragma unroll 4
        for (int c = 0; c < AKV; c++) {
            const float4 v0 = *(const float4*)(Vs + c * QP + tc * 8);
            const float4 v1 = *(const float4*)(Vs + c * QP + tc * 8 + 4);
#pragma unroll
            for (int i = 0; i < 4; i++) {
                const float p = Sc[(tr + 16 * i) * SP + c];
                o[i][0] += p * v0.x; o[i][1] += p * v0.y;
                o[i][2] += p * v0.z; o[i][3] += p * v0.w;
                o[i][4] += p * v1.x; o[i][5] += p * v1.y;
                o[i][6] += p * v1.z; o[i][7] += p * v1.w;
            }
        }
        __syncthreads();
    }

    // Normalize and write ctx[s, h*128 + d]
#pragma unroll
    for (int i = 0; i < 4; i++) {
        const int r = q0 + tr + 16 * i;
        const float inv = 1.0f / l_i[i];
        float4 w0 = make_float4(o[i][0] * inv, o[i][1] * inv,
                                o[i][2] * inv, o[i][3] * inv);
        float4 w1 = make_float4(o[i][4] * inv, o[i][5] * inv,
                                o[i][6] * inv, o[i][7] * inv);
        float* dst = g_ctx + (size_t)r * H_DIM + h * HD + tc * 8;
        *(float4*)dst = w0;
        *(float4*)(dst + 4) = w1;
    }
}

// ---------------------------------------------------------------------------
// Launch: QKV GEMM -> flash attention -> dense GEMM (+bias +residual)
// ---------------------------------------------------------------------------
extern "C" void kernel_launch(void* const* d_in, const int* in_sizes, int n_in,
                              void* d_out, int out_size)
{
    const float* hidden  = (const float*)d_in[0];
    const float* resid   = (const float*)d_in[1];
    const float* alibi   = (const float*)d_in[2];
    // d_in[3] = attention_mask (deterministic causal; computed analytically)
    const float* qkv_w   = (const float*)d_in[4];
    const float* qkv_b   = (const float*)d_in[5];
    const float* dense_w = (const float*)d_in[6];
    const float* dense_b = (const float*)d_in[7];
    float* out = (float*)d_out;

    float *fused_p, *ctx_p;
    cudaGetSymbolAddress((void**)&fused_p, g_fused);
    cudaGetSymbolAddress((void**)&ctx_p, g_ctx);

    cudaFuncSetAttribute(attn_kernel,
                         cudaFuncAttributeMaxDynamicSharedMemorySize, ATTN_SMEM);

    // 1) fused = hidden @ qkv_w^T + qkv_b   [2048, 12288]
    gemm_kernel<false><<<dim3(K3 / 128, S_LEN / 128), 256>>>(
        hidden, qkv_w, qkv_b, nullptr, fused_p, S_LEN, K3, H_DIM);

    // 2) attention -> g_ctx [2048, 4096]
    attn_kernel<<<dim3(S_LEN / AQ, NHEADS), 256, ATTN_SMEM>>>(alibi);

    // 3) out = ctx @ dense_w^T + dense_b + residual
    gemm_kernel<true><<<dim3(H_DIM / 128, S_LEN / 128), 256>>>(
        ctx_p, dense_w, dense_b, resid, out, S_LEN, H_DIM, H_DIM);
}

// round 6
// speedup vs baseline: 2.3236x; 2.3236x over previous
#include <cuda_runtime.h>
#include <stdint.h>
#include <math.h>

// Problem constants
#define S_LEN   2048
#define H_DIM   4096
#define NHEADS  32
#define HD      128
#define K3      12288            // 3*H
#define INV_NORM 0.08838834764831845f   // 1/sqrt(128)

typedef unsigned int u32;

// Scratch (device globals: allocation-free)
__device__ float g_fused[(size_t)S_LEN * K3];   // [S, NH, 3, HD]
__device__ float g_ctx[(size_t)S_LEN * H_DIM];  // [S, H]

// ---------------------------------------------------------------------------
// tf32 tensor-core GEMM: C[M,N] = A[M,K] @ Bw[N,K]^T + bias[N] (+ resid)
// 128x128x32 tile, 256 threads (8 warps), each warp 64x32 via m16n8k8 frags.
// ---------------------------------------------------------------------------
#define BM 128
#define BN 128
#define BK 32
#define SPITCH 36   // BK + 4 pad: bank = (4*row + col) % 32, conflict-free

__device__ __forceinline__ u32 f2tf32(float x) {
    u32 r;
    asm("cvt.rna.tf32.f32 %0, %1;" : "=r"(r) : "f"(x));
    return r;
}

__device__ __forceinline__ void mma_tf32(float c[4], const u32 a[4],
                                         const u32 b[2]) {
    asm volatile(
        "mma.sync.aligned.m16n8k8.row.col.f32.tf32.tf32.f32 "
        "{%0,%1,%2,%3}, {%4,%5,%6,%7}, {%8,%9}, {%0,%1,%2,%3};"
        : "+f"(c[0]), "+f"(c[1]), "+f"(c[2]), "+f"(c[3])
        : "r"(a[0]), "r"(a[1]), "r"(a[2]), "r"(a[3]), "r"(b[0]), "r"(b[1]));
}

template<bool ADD_RES>
__global__ __launch_bounds__(256) void gemm_tf32(
    const float* __restrict__ A, const float* __restrict__ Bw,
    const float* __restrict__ bias, const float* __restrict__ resid,
    float* __restrict__ C, int M, int N, int K)
{
    __shared__ u32 As[BM * SPITCH];
    __shared__ u32 Bs[BN * SPITCH];

    const int tid  = threadIdx.x;
    const int warp = tid >> 5;
    const int lane = tid & 31;
    const int wm   = (warp & 1) * 64;    // warp M offset (2 warps in M)
    const int wn   = (warp >> 1) * 32;   // warp N offset (4 warps in N)
    const int lr   = tid >> 3;           // 0..31 load row base
    const int lc   = (tid & 7) * 4;      // load col (float4)

    const float* Ab = A  + (size_t)blockIdx.y * BM * K;
    const float* Bb = Bw + (size_t)blockIdx.x * BN * K;

    float acc[4][4][4];
#pragma unroll
    for (int i = 0; i < 4; i++)
#pragma unroll
        for (int j = 0; j < 4; j++)
#pragma unroll
            for (int r = 0; r < 4; r++) acc[i][j][r] = 0.f;

    // Prologue: load tile 0 into smem (with rna tf32 rounding)
#pragma unroll
    for (int i = 0; i < 4; i++) {
        const int row = lr + i * 32;
        float4 a4 = *(const float4*)(Ab + (size_t)row * K + lc);
        float4 b4 = *(const float4*)(Bb + (size_t)row * K + lc);
        u32* as = &As[row * SPITCH + lc];
        u32* bs = &Bs[row * SPITCH + lc];
        as[0] = f2tf32(a4.x); as[1] = f2tf32(a4.y);
        as[2] = f2tf32(a4.z); as[3] = f2tf32(a4.w);
        bs[0] = f2tf32(b4.x); bs[1] = f2tf32(b4.y);
        bs[2] = f2tf32(b4.z); bs[3] = f2tf32(b4.w);
    }
    __syncthreads();

    for (int k0 = 0; k0 < K; k0 += BK) {
        const bool more = (k0 + BK) < K;
        float4 pa[4], pb[4];
        if (more) {
#pragma unroll
            for (int i = 0; i < 4; i++) {
                const int row = lr + i * 32;
                pa[i] = *(const float4*)(Ab + (size_t)row * K + k0 + BK + lc);
                pb[i] = *(const float4*)(Bb + (size_t)row * K + k0 + BK + lc);
            }
        }

        // Compute current tile
#pragma unroll
        for (int kk = 0; kk < BK; kk += 8) {
            u32 af[4][4], bf[4][2];
            const int kq = kk + (lane & 3);
#pragma unroll
            for (int mf = 0; mf < 4; mf++) {
                const int r0 = wm + mf * 16 + (lane >> 2);
                af[mf][0] = As[r0 * SPITCH + kq];
                af[mf][1] = As[(r0 + 8) * SPITCH + kq];
                af[mf][2] = As[r0 * SPITCH + kq + 4];
                af[mf][3] = As[(r0 + 8) * SPITCH + kq + 4];
            }
#pragma unroll
            for (int nf = 0; nf < 4; nf++) {
                const int c0 = wn + nf * 8 + (lane >> 2);
                bf[nf][0] = Bs[c0 * SPITCH + kq];
                bf[nf][1] = Bs[c0 * SPITCH + kq + 4];
            }
#pragma unroll
            for (int mf = 0; mf < 4; mf++)
#pragma unroll
                for (int nf = 0; nf < 4; nf++)
                    mma_tf32(acc[mf][nf], af[mf], bf[nf]);
        }
        __syncthreads();

        if (more) {
#pragma unroll
            for (int i = 0; i < 4; i++) {
                const int row = lr + i * 32;
                u32* as = &As[row * SPITCH + lc];
                u32* bs = &Bs[row * SPITCH + lc];
                as[0] = f2tf32(pa[i].x); as[1] = f2tf32(pa[i].y);
                as[2] = f2tf32(pa[i].z); as[3] = f2tf32(pa[i].w);
                bs[0] = f2tf32(pb[i].x); bs[1] = f2tf32(pb[i].y);
                bs[2] = f2tf32(pb[i].z); bs[3] = f2tf32(pb[i].w);
            }
            __syncthreads();
        }
    }

    // Epilogue
#pragma unroll
    for (int mf = 0; mf < 4; mf++) {
        const int row = blockIdx.y * BM + wm + mf * 16 + (lane >> 2);
#pragma unroll
        for (int nf = 0; nf < 4; nf++) {
            const int col = blockIdx.x * BN + wn + nf * 8 + 2 * (lane & 3);
            const float b0 = bias[col], b1 = bias[col + 1];
            float v0 = acc[mf][nf][0] + b0;
            float v1 = acc[mf][nf][1] + b1;
            float v2 = acc[mf][nf][2] + b0;
            float v3 = acc[mf][nf][3] + b1;
            if (ADD_RES) {
                v0 += resid[(size_t)row * N + col];
                v1 += resid[(size_t)row * N + col + 1];
                v2 += resid[(size_t)(row + 8) * N + col];
                v3 += resid[(size_t)(row + 8) * N + col + 1];
            }
            *(float2*)(C + (size_t)row * N + col)       = make_float2(v0, v1);
            *(float2*)(C + (size_t)(row + 8) * N + col) = make_float2(v2, v3);
        }
    }
}

// ---------------------------------------------------------------------------
// Flash attention (fp32, causal + alibi), unchanged (passing since R1).
// ---------------------------------------------------------------------------
#define AQ  64
#define AKV 64
#define QP  132
#define SP  68
#define NEG_INF -1e30f
#define ATTN_SMEM ((AQ*QP + 2*AKV*QP + AQ*SP) * 4)

__global__ __launch_bounds__(256) void attn_kernel(const float* __restrict__ alibi)
{
    extern __shared__ float sm[];
    float* Qs = sm;
    float* Ks = Qs + AQ * QP;
    float* Vs = Ks + AKV * QP;
    float* Sc = Vs + AKV * QP;

    const int q0  = blockIdx.x * AQ;
    const int h   = blockIdx.y;
    const int tid = threadIdx.x;
    const int tr  = tid >> 4;
    const int tc  = tid & 15;

    {
        const float* qbase = g_fused + (size_t)q0 * K3 + h * 384;
        for (int idx = tid; idx < AQ * 32; idx += 256) {
            const int r  = idx >> 5;
            const int c4 = (idx & 31) << 2;
            *(float4*)(Qs + r * QP + c4) =
                *(const float4*)(qbase + (size_t)r * K3 + c4);
        }
    }

    float m_i[4], l_i[4], o[4][8];
#pragma unroll
    for (int i = 0; i < 4; i++) {
        m_i[i] = NEG_INF; l_i[i] = 0.f;
#pragma unroll
        for (int d = 0; d < 8; d++) o[i][d] = 0.f;
    }

    const float* alibi_h = alibi + (size_t)h * S_LEN;
    const int nkt = (q0 / AKV) + 1;

    for (int kt = 0; kt < nkt; kt++) {
        const int kc = kt * AKV;
        {
            const float* kbase = g_fused + (size_t)kc * K3 + h * 384 + 128;
            const float* vbase = kbase + 128;
            for (int idx = tid; idx < AKV * 32; idx += 256) {
                const int r  = idx >> 5;
                const int c4 = (idx & 31) << 2;
                *(float4*)(Ks + r * QP + c4) =
                    *(const float4*)(kbase + (size_t)r * K3 + c4);
                *(float4*)(Vs + r * QP + c4) =
                    *(const float4*)(vbase + (size_t)r * K3 + c4);
            }
        }
        __syncthreads();

        float acc[4][4];
#pragma unroll
        for (int i = 0; i < 4; i++)
#pragma unroll
            for (int j = 0; j < 4; j++) acc[i][j] = 0.f;

#pragma unroll 8
        for (int k = 0; k < HD; k += 4) {
            float4 qv[4], kv[4];
#pragma unroll
            for (int i = 0; i < 4; i++)
                qv[i] = *(const float4*)(Qs + (tr + 16 * i) * QP + k);
#pragma unroll
            for (int j = 0; j < 4; j++)
                kv[j] = *(const float4*)(Ks + (tc + 16 * j) * QP + k);
#pragma unroll
            for (int i = 0; i < 4; i++)
#pragma unroll
                for (int j = 0; j < 4; j++) {
                    acc[i][j] += qv[i].x * kv[j].x;
                    acc[i][j] += qv[i].y * kv[j].y;
                    acc[i][j] += qv[i].z * kv[j].z;
                    acc[i][j] += qv[i].w * kv[j].w;
                }
        }

#pragma unroll
        for (int i = 0; i < 4; i++) {
            const int r = q0 + tr + 16 * i;
            float s[4];
            float mx = NEG_INF;
#pragma unroll
            for (int j = 0; j < 4; j++) {
                const int c = kc + tc + 16 * j;
                s[j] = (c <= r) ? acc[i][j] * INV_NORM + __ldg(&alibi_h[c])
                                : NEG_INF;
                mx = fmaxf(mx, s[j]);
            }
            mx = fmaxf(mx, __shfl_xor_sync(0xffffffffu, mx, 1));
            mx = fmaxf(mx, __shfl_xor_sync(0xffffffffu, mx, 2));
            mx = fmaxf(mx, __shfl_xor_sync(0xffffffffu, mx, 4));
            mx = fmaxf(mx, __shfl_xor_sync(0xffffffffu, mx, 8));

            const float m_new = fmaxf(m_i[i], mx);
            const float scale = __expf(m_i[i] - m_new);
            m_i[i] = m_new;

            float ps = 0.f;
#pragma unroll
            for (int j = 0; j < 4; j++) {
                const float p = __expf(s[j] - m_new);
                Sc[(tr + 16 * i) * SP + tc + 16 * j] = p;
                ps += p;
            }
            ps += __shfl_xor_sync(0xffffffffu, ps, 1);
            ps += __shfl_xor_sync(0xffffffffu, ps, 2);
            ps += __shfl_xor_sync(0xffffffffu, ps, 4);
            ps += __shfl_xor_sync(0xffffffffu, ps, 8);

            l_i[i] = l_i[i] * scale + ps;
#pragma unroll
            for (int d = 0; d < 8; d++) o[i][d] *= scale;
        }
        __syncthreads();

#pragma unroll 4
        for (int c = 0; c < AKV; c++) {
            const float4 v0 = *(const float4*)(Vs + c * QP + tc * 8);
            const float4 v1 = *(const float4*)(Vs + c * QP + tc * 8 + 4);
#pragma unroll
            for (int i = 0; i < 4; i++) {
                const float p = Sc[(tr + 16 * i) * SP + c];
                o[i][0] += p * v0.x; o[i][1] += p * v0.y;
                o[i][2] += p * v0.z; o[i][3] += p * v0.w;
                o[i][4] += p * v1.x; o[i][5] += p * v1.y;
                o[i][6] += p * v1.z; o[i][7] += p * v1.w;
            }
        }
        __syncthreads();
    }

#pragma unroll
    for (int i = 0; i < 4; i++) {
        const int r = q0 + tr + 16 * i;
        const float inv = 1.0f / l_i[i];
        float4 w0 = make_float4(o[i][0] * inv, o[i][1] * inv,
                                o[i][2] * inv, o[i][3] * inv);
        float4 w1 = make_float4(o[i][4] * inv, o[i][5] * inv,
                                o[i][6] * inv, o[i][7] * inv);
        float* dst = g_ctx + (size_t)r * H_DIM + h * HD + tc * 8;
        *(float4*)dst = w0;
        *(float4*)(dst + 4) = w1;
    }
}

// ---------------------------------------------------------------------------
extern "C" void kernel_launch(void* const* d_in, const int* in_sizes, int n_in,
                              void* d_out, int out_size)
{
    const float* hidden  = (const float*)d_in[0];
    const float* resid   = (const float*)d_in[1];
    const float* alibi   = (const float*)d_in[2];
    const float* qkv_w   = (const float*)d_in[4];
    const float* qkv_b   = (const float*)d_in[5];
    const float* dense_w = (const float*)d_in[6];
    const float* dense_b = (const float*)d_in[7];
    float* out = (float*)d_out;

    float *fused_p, *ctx_p;
    cudaGetSymbolAddress((void**)&fused_p, g_fused);
    cudaGetSymbolAddress((void**)&ctx_p, g_ctx);

    cudaFuncSetAttribute(attn_kernel,
                         cudaFuncAttributeMaxDynamicSharedMemorySize, ATTN_SMEM);

    // 1) fused = hidden @ qkv_w^T + qkv_b   [2048, 12288]
    gemm_tf32<false><<<dim3(K3 / BN, S_LEN / BM), 256>>>(
        hidden, qkv_w, qkv_b, nullptr, fused_p, S_LEN, K3, H_DIM);

    // 2) attention -> g_ctx [2048, 4096]
    attn_kernel<<<dim3(S_LEN / AQ, NHEADS), 256, ATTN_SMEM>>>(alibi);

    // 3) out = ctx @ dense_w^T + dense_b + residual
    gemm_tf32<true><<<dim3(H_DIM / BN, S_LEN / BM), 256>>>(
        ctx_p, dense_w, dense_b, resid, out, S_LEN, H_DIM, H_DIM);
}

// round 7
// speedup vs baseline: 2.4823x; 1.0683x over previous
#include <cuda_runtime.h>
#include <stdint.h>
#include <math.h>

// Problem constants
#define S_LEN   2048
#define H_DIM   4096
#define NHEADS  32
#define HD      128
#define K3      12288            // 3*H
#define INV_NORM 0.08838834764831845f   // 1/sqrt(128)

typedef unsigned int u32;

// Scratch (device globals: allocation-free)
__device__ float g_fused[(size_t)S_LEN * K3];   // [S, NH, 3, HD]
__device__ float g_ctx[(size_t)S_LEN * H_DIM];  // [S, H]

// ---------------------------------------------------------------------------
// tf32 tensor-core GEMM: C[M,N] = A[M,K] @ Bw[N,K]^T + bias[N] (+ resid)
// 128x128x32 tile, 256 threads (8 warps), warp tile 64x32 (m16n8k8 frags).
// cp.async double-buffered raw-fp32 smem; tf32 cvt at fragment load.
// ---------------------------------------------------------------------------
#define BM 128
#define BN 128
#define BK 32
#define SPITCH 36                 // bank = (4*row + col) % 32 -> conflict-free
#define TILE_WORDS (BM * SPITCH)  // one A or B buffer
#define GEMM_SMEM (4 * TILE_WORDS * 4)   // 2 bufs x (A+B) x 4B = 73728 B

__device__ __forceinline__ u32 f2tf32(float x) {
    u32 r;
    asm("cvt.rna.tf32.f32 %0, %1;" : "=r"(r) : "f"(x));
    return r;
}

__device__ __forceinline__ void mma_tf32(float c[4], const u32 a[4],
                                         const u32 b[2]) {
    asm volatile(
        "mma.sync.aligned.m16n8k8.row.col.f32.tf32.tf32.f32 "
        "{%0,%1,%2,%3}, {%4,%5,%6,%7}, {%8,%9}, {%0,%1,%2,%3};"
        : "+f"(c[0]), "+f"(c[1]), "+f"(c[2]), "+f"(c[3])
        : "r"(a[0]), "r"(a[1]), "r"(a[2]), "r"(a[3]), "r"(b[0]), "r"(b[1]));
}

__device__ __forceinline__ void cpasync16(float* dst_smem, const float* src) {
    u32 sd = (u32)__cvta_generic_to_shared(dst_smem);
    asm volatile("cp.async.cg.shared.global [%0], [%1], 16;"
                 :: "r"(sd), "l"(src));
}

template<bool ADD_RES>
__global__ __launch_bounds__(256, 2) void gemm_tf32(
    const float* __restrict__ A, const float* __restrict__ Bw,
    const float* __restrict__ bias, const float* __restrict__ resid,
    float* __restrict__ C, int M, int N, int K)
{
    extern __shared__ float sm[];
    // layout: [buf0 A][buf1 A][buf0 B][buf1 B]
    float* Abuf[2] = { sm,                  sm + TILE_WORDS };
    float* Bbuf[2] = { sm + 2 * TILE_WORDS, sm + 3 * TILE_WORDS };

    const int tid  = threadIdx.x;
    const int warp = tid >> 5;
    const int lane = tid & 31;
    const int wm   = (warp & 1) * 64;    // warp M offset (2 warps in M)
    const int wn   = (warp >> 1) * 32;   // warp N offset (4 warps in N)
    const int lr   = tid >> 3;           // 0..31 load row base
    const int lc   = (tid & 7) * 4;      // load col (float4 granule)

    const float* Ab = A  + (size_t)blockIdx.y * BM * K;
    const float* Bb = Bw + (size_t)blockIdx.x * BN * K;

    float acc[4][4][4];
#pragma unroll
    for (int i = 0; i < 4; i++)
#pragma unroll
        for (int j = 0; j < 4; j++)
#pragma unroll
            for (int r = 0; r < 4; r++) acc[i][j][r] = 0.f;

    // Prologue: async-copy tile 0 into buffer 0
#pragma unroll
    for (int i = 0; i < 4; i++) {
        const int row = lr + i * 32;
        cpasync16(&Abuf[0][row * SPITCH + lc], Ab + (size_t)row * K + lc);
        cpasync16(&Bbuf[0][row * SPITCH + lc], Bb + (size_t)row * K + lc);
    }
    asm volatile("cp.async.commit_group;");
    asm volatile("cp.async.wait_group 0;");
    __syncthreads();

    const int NT = K / BK;
    for (int t = 0; t < NT; t++) {
        const int buf = t & 1;
        // Kick off next tile's copies into the other buffer
        if (t + 1 < NT) {
            const int nxt = buf ^ 1;
            const int koff = (t + 1) * BK;
#pragma unroll
            for (int i = 0; i < 4; i++) {
                const int row = lr + i * 32;
                cpasync16(&Abuf[nxt][row * SPITCH + lc],
                          Ab + (size_t)row * K + koff + lc);
                cpasync16(&Bbuf[nxt][row * SPITCH + lc],
                          Bb + (size_t)row * K + koff + lc);
            }
        }
        asm volatile("cp.async.commit_group;");

        const float* As = Abuf[buf];
        const float* Bs = Bbuf[buf];

        // Compute current tile
#pragma unroll
        for (int kk = 0; kk < BK; kk += 8) {
            u32 af[4][4], bf[4][2];
            const int kq = kk + (lane & 3);
#pragma unroll
            for (int mf = 0; mf < 4; mf++) {
                const int r0 = wm + mf * 16 + (lane >> 2);
                af[mf][0] = f2tf32(As[r0 * SPITCH + kq]);
                af[mf][1] = f2tf32(As[(r0 + 8) * SPITCH + kq]);
                af[mf][2] = f2tf32(As[r0 * SPITCH + kq + 4]);
                af[mf][3] = f2tf32(As[(r0 + 8) * SPITCH + kq + 4]);
            }
#pragma unroll
            for (int nf = 0; nf < 4; nf++) {
                const int c0 = wn + nf * 8 + (lane >> 2);
                bf[nf][0] = f2tf32(Bs[c0 * SPITCH + kq]);
                bf[nf][1] = f2tf32(Bs[c0 * SPITCH + kq + 4]);
            }
#pragma unroll
            for (int mf = 0; mf < 4; mf++)
#pragma unroll
                for (int nf = 0; nf < 4; nf++)
                    mma_tf32(acc[mf][nf], af[mf], bf[nf]);
        }

        asm volatile("cp.async.wait_group 0;");
        __syncthreads();
    }

    // Epilogue
#pragma unroll
    for (int mf = 0; mf < 4; mf++) {
        const int row = blockIdx.y * BM + wm + mf * 16 + (lane >> 2);
#pragma unroll
        for (int nf = 0; nf < 4; nf++) {
            const int col = blockIdx.x * BN + wn + nf * 8 + 2 * (lane & 3);
            const float b0 = bias[col], b1 = bias[col + 1];
            float v0 = acc[mf][nf][0] + b0;
            float v1 = acc[mf][nf][1] + b1;
            float v2 = acc[mf][nf][2] + b0;
            float v3 = acc[mf][nf][3] + b1;
            if (ADD_RES) {
                v0 += resid[(size_t)row * N + col];
                v1 += resid[(size_t)row * N + col + 1];
                v2 += resid[(size_t)(row + 8) * N + col];
                v3 += resid[(size_t)(row + 8) * N + col + 1];
            }
            *(float2*)(C + (size_t)row * N + col)       = make_float2(v0, v1);
            *(float2*)(C + (size_t)(row + 8) * N + col) = make_float2(v2, v3);
        }
    }
}

// ---------------------------------------------------------------------------
// Flash attention (fp32, causal + alibi), unchanged (passing since R1).
// ---------------------------------------------------------------------------
#define AQ  64
#define AKV 64
#define QP  132
#define SP  68
#define NEG_INF -1e30f
#define ATTN_SMEM ((AQ*QP + 2*AKV*QP + AQ*SP) * 4)

__global__ __launch_bounds__(256) void attn_kernel(const float* __restrict__ alibi)
{
    extern __shared__ float smref[];
    float* Qs = smref;
    float* Ks = Qs + AQ * QP;
    float* Vs = Ks + AKV * QP;
    float* Sc = Vs + AKV * QP;

    const int q0  = blockIdx.x * AQ;
    const int h   = blockIdx.y;
    const int tid = threadIdx.x;
    const int tr  = tid >> 4;
    const int tc  = tid & 15;

    {
        const float* qbase = g_fused + (size_t)q0 * K3 + h * 384;
        for (int idx = tid; idx < AQ * 32; idx += 256) {
            const int r  = idx >> 5;
            const int c4 = (idx & 31) << 2;
            *(float4*)(Qs + r * QP + c4) =
                *(const float4*)(qbase + (size_t)r * K3 + c4);
        }
    }

    float m_i[4], l_i[4], o[4][8];
#pragma unroll
    for (int i = 0; i < 4; i++) {
        m_i[i] = NEG_INF; l_i[i] = 0.f;
#pragma unroll
        for (int d = 0; d < 8; d++) o[i][d] = 0.f;
    }

    const float* alibi_h = alibi + (size_t)h * S_LEN;
    const int nkt = (q0 / AKV) + 1;

    for (int kt = 0; kt < nkt; kt++) {
        const int kc = kt * AKV;
        {
            const float* kbase = g_fused + (size_t)kc * K3 + h * 384 + 128;
            const float* vbase = kbase + 128;
            for (int idx = tid; idx < AKV * 32; idx += 256) {
                const int r  = idx >> 5;
                const int c4 = (idx & 31) << 2;
                *(float4*)(Ks + r * QP + c4) =
                    *(const float4*)(kbase + (size_t)r * K3 + c4);
                *(float4*)(Vs + r * QP + c4) =
                    *(const float4*)(vbase + (size_t)r * K3 + c4);
            }
        }
        __syncthreads();

        float acc[4][4];
#pragma unroll
        for (int i = 0; i < 4; i++)
#pragma unroll
            for (int j = 0; j < 4; j++) acc[i][j] = 0.f;

#pragma unroll 8
        for (int k = 0; k < HD; k += 4) {
            float4 qv[4], kv[4];
#pragma unroll
            for (int i = 0; i < 4; i++)
                qv[i] = *(const float4*)(Qs + (tr + 16 * i) * QP + k);
#pragma unroll
            for (int j = 0; j < 4; j++)
                kv[j] = *(const float4*)(Ks + (tc + 16 * j) * QP + k);
#pragma unroll
            for (int i = 0; i < 4; i++)
#pragma unroll
                for (int j = 0; j < 4; j++) {
                    acc[i][j] += qv[i].x * kv[j].x;
                    acc[i][j] += qv[i].y * kv[j].y;
                    acc[i][j] += qv[i].z * kv[j].z;
                    acc[i][j] += qv[i].w * kv[j].w;
                }
        }

#pragma unroll
        for (int i = 0; i < 4; i++) {
            const int r = q0 + tr + 16 * i;
            float s[4];
            float mx = NEG_INF;
#pragma unroll
            for (int j = 0; j < 4; j++) {
                const int c = kc + tc + 16 * j;
                s[j] = (c <= r) ? acc[i][j] * INV_NORM + __ldg(&alibi_h[c])
                                : NEG_INF;
                mx = fmaxf(mx, s[j]);
            }
            mx = fmaxf(mx, __shfl_xor_sync(0xffffffffu, mx, 1));
            mx = fmaxf(mx, __shfl_xor_sync(0xffffffffu, mx, 2));
            mx = fmaxf(mx, __shfl_xor_sync(0xffffffffu, mx, 4));
            mx = fmaxf(mx, __shfl_xor_sync(0xffffffffu, mx, 8));

            const float m_new = fmaxf(m_i[i], mx);
            const float scale = __expf(m_i[i] - m_new);
            m_i[i] = m_new;

            float ps = 0.f;
#pragma unroll
            for (int j = 0; j < 4; j++) {
                const float p = __expf(s[j] - m_new);
                Sc[(tr + 16 * i) * SP + tc + 16 * j] = p;
                ps += p;
            }
            ps += __shfl_xor_sync(0xffffffffu, ps, 1);
            ps += __shfl_xor_sync(0xffffffffu, ps, 2);
            ps += __shfl_xor_sync(0xffffffffu, ps, 4);
            ps += __shfl_xor_sync(0xffffffffu, ps, 8);

            l_i[i] = l_i[i] * scale + ps;
#pragma unroll
            for (int d = 0; d < 8; d++) o[i][d] *= scale;
        }
        __syncthreads();

#pragma unroll 4
        for (int c = 0; c < AKV; c++) {
            const float4 v0 = *(const float4*)(Vs + c * QP + tc * 8);
            const float4 v1 = *(const float4*)(Vs + c * QP + tc * 8 + 4);
#pragma unroll
            for (int i = 0; i < 4; i++) {
                const float p = Sc[(tr + 16 * i) * SP + c];
                o[i][0] += p * v0.x; o[i][1] += p * v0.y;
                o[i][2] += p * v0.z; o[i][3] += p * v0.w;
                o[i][4] += p * v1.x; o[i][5] += p * v1.y;
                o[i][6] += p * v1.z; o[i][7] += p * v1.w;
            }
        }
        __syncthreads();
    }

#pragma unroll
    for (int i = 0; i < 4; i++) {
        const int r = q0 + tr + 16 * i;
        const float inv = 1.0f / l_i[i];
        float4 w0 = make_float4(o[i][0] * inv, o[i][1] * inv,
                                o[i][2] * inv, o[i][3] * inv);
        float4 w1 = make_float4(o[i][4] * inv, o[i][5] * inv,
                                o[i][6] * inv, o[i][7] * inv);
        float* dst = g_ctx + (size_t)r * H_DIM + h * HD + tc * 8;
        *(float4*)dst = w0;
        *(float4*)(dst + 4) = w1;
    }
}

// ---------------------------------------------------------------------------
extern "C" void kernel_launch(void* const* d_in, const int* in_sizes, int n_in,
                              void* d_out, int out_size)
{
    const float* hidden  = (const float*)d_in[0];
    const float* resid   = (const float*)d_in[1];
    const float* alibi   = (const float*)d_in[2];
    const float* qkv_w   = (const float*)d_in[4];
    const float* qkv_b   = (const float*)d_in[5];
    const float* dense_w = (const float*)d_in[6];
    const float* dense_b = (const float*)d_in[7];
    float* out = (float*)d_out;

    float *fused_p, *ctx_p;
    cudaGetSymbolAddress((void**)&fused_p, g_fused);
    cudaGetSymbolAddress((void**)&ctx_p, g_ctx);

    cudaFuncSetAttribute(gemm_tf32<false>,
                         cudaFuncAttributeMaxDynamicSharedMemorySize, GEMM_SMEM);
    cudaFuncSetAttribute(gemm_tf32<true>,
                         cudaFuncAttributeMaxDynamicSharedMemorySize, GEMM_SMEM);
    cudaFuncSetAttribute(attn_kernel,
                         cudaFuncAttributeMaxDynamicSharedMemorySize, ATTN_SMEM);

    // 1) fused = hidden @ qkv_w^T + qkv_b   [2048, 12288]
    gemm_tf32<false><<<dim3(K3 / BN, S_LEN / BM), 256, GEMM_SMEM>>>(
        hidden, qkv_w, qkv_b, nullptr, fused_p, S_LEN, K3, H_DIM);

    // 2) attention -> g_ctx [2048, 4096]
    attn_kernel<<<dim3(S_LEN / AQ, NHEADS), 256, ATTN_SMEM>>>(alibi);

    // 3) out = ctx @ dense_w^T + dense_b + residual
    gemm_tf32<true><<<dim3(H_DIM / BN, S_LEN / BM), 256, GEMM_SMEM>>>(
        ctx_p, dense_w, dense_b, resid, out, S_LEN, H_DIM, H_DIM);
}